// round 5
// baseline (speedup 1.0000x reference)
#include <cuda_runtime.h>
#include <cfloat>
#include <climits>
#include <math.h>

// Beam search step: P=32 prompts, D=8 beams, V=128000, S=2048.
// Ordering by alive_lp + log(p) == ordering by m = p * exp(alive_lp) (monotone).
// k0: per-prompt threshold tau = min of 16 disjoint chunk maxima (<= global 16th).
// k1: batched max-filter seeded with tau -> slow path is rare; 1 ballot / 16 elems.

#define P_ 32
#define D_ 8
#define V_ 128000
#define S_ 2048
#define NBLK 16          // blocks per prompt in k1 (2 per beam)
#define CHUNK 64000      // elements per k1 block (V/2)
#define NCAND 2048       // NBLK * 8 warps * 16
#define NC0 256          // 2 blocks * 8 warps * 16 (beam-0 lists)
#define EOS_ID 2
#define MASK_INF 10000000.0f
#define PADV (-FLT_MAX)

// output layout (flat float32, tuple concat order)
#define OFF_ATTN 0
#define OFF_ASEQ 256
#define OFF_ALP  524544
#define OFF_FSEQ 524800
#define OFF_FLP  1049088

__device__ float g_cand_val[P_ * NCAND];
__device__ int   g_cand_idx[P_ * NCAND];
__device__ float g_c0_val[P_ * NC0];
__device__ int   g_c0_idx[P_ * NC0];
__device__ int4  g_desc[2 * P_ * D_];   // {buf(0=alive,1=fin), src_beam, token, subpos(-1 none)}
__device__ float g_tau[P_];             // scaled-space threshold (<= global 16th)
__device__ float g_tau0[P_];            // beam-0 raw threshold  (<= beam0 16th)

#define FULLM 0xffffffffu

__device__ __forceinline__ float max4(float4 v) {
    return fmaxf(fmaxf(v.x, v.y), fmaxf(v.z, v.w));
}

// Warp-cooperative insertion into a shared sorted top-16 list (desc value, asc index).
__device__ __forceinline__ void topk_insert(float v, int idx, float& th, int& thi,
                                            volatile float* lv, volatile int* li) {
    int lane = threadIdx.x & 31;
    bool want = (v > th) || (v == th && idx < thi);
    while (true) {
        unsigned mask = __ballot_sync(FULLM, want);
        if (!mask) break;
        int leader = __ffs(mask) - 1;
        if (lane == leader) {
            int pos = 16;
            for (int j = 15; j >= 0; j--) {
                if ((v > lv[j]) || (v == lv[j] && idx < li[j])) pos = j; else break;
            }
            if (pos < 16) {
                for (int j = 15; j > pos; j--) { lv[j] = lv[j-1]; li[j] = li[j-1]; }
                lv[pos] = v; li[pos] = idx;
            }
            want = false;
        }
        __syncwarp();
        th = lv[15]; thi = li[15];
        want = want && ((v > th) || (v == th && idx < thi));
    }
}

// ---------------- Kernel 0: per-prompt thresholds (pure max/min reductions) ---
// 16 warps; warp w = (beam d=w/2, half h=w%2) scans 4096 contiguous elements.
// Each lane takes 128 contiguous elems. tau = min over the 16 scaled chunk maxima.
// tau0 = min over 16 sub-chunk maxima (512 elems each) of beam 0's 8192 sample.
__global__ void __launch_bounds__(512)
k0_tau(const float* __restrict__ probs, const float* __restrict__ alive_lp) {
    int p = blockIdx.x;
    int t = threadIdx.x, w = t >> 5, lane = t & 31;
    int d = w >> 1, h = w & 1;
    __shared__ float s_max[16];
    __shared__ float s_max0[16];

    const float4* b4 = (const float4*)(probs + (long)(p * D_ + d) * V_ + h * 4096) + lane * 32;
    float m = -FLT_MAX;
#pragma unroll
    for (int i = 0; i < 32; i++) m = fmaxf(m, max4(b4[i]));

    float wm = m;
#pragma unroll
    for (int off = 16; off; off >>= 1) wm = fmaxf(wm, __shfl_xor_sync(FULLM, wm, off));
    if (lane == 0) s_max[w] = wm * expf(alive_lp[p * D_ + d]);

    if (d == 0) {  // sub-chunk maxima: groups of 4 lanes = 512 elements
        float sm = m;
        sm = fmaxf(sm, __shfl_xor_sync(FULLM, sm, 1));
        sm = fmaxf(sm, __shfl_xor_sync(FULLM, sm, 2));
        if ((lane & 3) == 0) s_max0[w * 8 + (lane >> 2)] = sm;
    }
    __syncthreads();
    if (t == 0) {
        float tau = FLT_MAX, tau0 = FLT_MAX;
        for (int i = 0; i < 16; i++) { tau = fminf(tau, s_max[i]); tau0 = fminf(tau0, s_max0[i]); }
        g_tau[p] = tau; g_tau0[p] = tau0;
    }
}

// ---------------- Kernel 1: scan probs, collect per-warp top-16 candidates ----
__global__ void __launch_bounds__(256)
k1_scan(const float* __restrict__ probs, const float* __restrict__ alive_lp) {
    int blk = blockIdx.x;
    int p = blk >> 4;
    int b = blk & 15;
    int d = b >> 1;
    int half = b & 1;
    int t = threadIdx.x, w = t >> 5, lane = t & 31;

    __shared__ float sv[8][16];  __shared__ int si[8][16];
    __shared__ float sv0[8][16]; __shared__ int si0[8][16];
    if (lane < 16) {
        sv[w][lane] = -FLT_MAX;  si[w][lane] = INT_MAX;
        sv0[w][lane] = -FLT_MAX; si0[w][lane] = INT_MAX;
    }
    __syncwarp();

    float scale = expf(alive_lp[p * D_ + d]);
    float tau  = g_tau[p];
    float tau0 = g_tau0[p];
    const float4* b4 = (const float4*)(probs + (long)(p * D_ + d) * V_ + half * CHUNK);
    int fb0 = d * V_ + half * CHUNK;
    const int N4 = CHUNK / 4;                 // 16000 float4s per block
    float thm = tau;  int thmi = INT_MAX;
    float th0 = tau0; int th0i = INT_MAX;
    bool do0 = (d == 0);
    const float4 pad4 = make_float4(PADV, PADV, PADV, PADV);

    for (int j0 = t; j0 < N4; j0 += 1024) {
        int j1 = j0 + 256, j2 = j0 + 512, j3 = j0 + 768;
        float4 va = __ldcs(b4 + j0);
        float4 vb = (j1 < N4) ? __ldcs(b4 + j1) : pad4;
        float4 vc = (j2 < N4) ? __ldcs(b4 + j2) : pad4;
        float4 vd = (j3 < N4) ? __ldcs(b4 + j3) : pad4;

        float vmax = fmaxf(fmaxf(max4(va), max4(vb)), fmaxf(max4(vc), max4(vd)));
        bool wm = (vmax * scale >= thm);      // >= keeps index tie-break exact
        bool w0 = do0 && (vmax >= th0);

        if (__ballot_sync(FULLM, wm | w0)) {  // rare: tau-seeded threshold
            float4 q[4] = {va, vb, vc, vd};
            int js[4] = {j0, j1, j2, j3};
#pragma unroll
            for (int u = 0; u < 4; u++) {
                bool ok = (js[u] < N4);
                int fb = fb0 + js[u] * 4;
                float vx[4] = {q[u].x, q[u].y, q[u].z, q[u].w};
#pragma unroll
                for (int c = 0; c < 4; c++) {
                    int idx = ok ? (fb + c) : INT_MAX;
                    topk_insert(vx[c] * scale, idx, thm, thmi, sv[w], si[w]);
                }
            }
            if (do0) {
#pragma unroll
                for (int u = 0; u < 4; u++) {
                    bool ok = (js[u] < N4);
                    int fb = fb0 + js[u] * 4;
                    float vx[4] = {q[u].x, q[u].y, q[u].z, q[u].w};
#pragma unroll
                    for (int c = 0; c < 4; c++) {
                        int idx = ok ? (fb + c) : INT_MAX;
                        topk_insert(vx[c], idx, th0, th0i, sv0[w], si0[w]);
                    }
                }
            }
            __syncwarp();
            // Guard: never let the working threshold fall below tau (pads are
            // -FLT_MAX while the list is not yet full). Dropping <tau is safe.
            thm = fmaxf(sv[w][15], tau);  thmi = si[w][15];
            if (do0) { th0 = fmaxf(sv0[w][15], tau0); th0i = si0[w][15]; }
        }
    }
    __syncwarp();
    if (lane < 16) {
        int cb = p * NCAND + (b * 8 + w) * 16 + lane;
        g_cand_val[cb] = sv[w][lane];
        g_cand_idx[cb] = si[w][lane];
        if (do0) {
            int c0 = p * NC0 + (half * 8 + w) * 16 + lane;
            g_c0_val[c0] = sv0[w][lane];
            g_c0_idx[c0] = si0[w][lane];
        }
    }
}

// Merge 128 shared candidates into sorted top-16 (one warp).
__device__ __forceinline__ void warp_merge128(volatile float* svals, volatile int* sidx,
                                              volatile float* outv, volatile int* outi) {
    int lane = threadIdx.x & 31;
    float mv[4]; int mi[4];
#pragma unroll
    for (int c = 0; c < 4; c++) { mv[c] = svals[lane * 4 + c]; mi[c] = sidx[lane * 4 + c]; }
    for (int k = 0; k < 16; k++) {
        float bv = mv[0]; int bi = mi[0];
#pragma unroll
        for (int c = 1; c < 4; c++)
            if (mv[c] > bv || (mv[c] == bv && mi[c] < bi)) { bv = mv[c]; bi = mi[c]; }
#pragma unroll
        for (int off = 16; off; off >>= 1) {
            float ov = __shfl_xor_sync(FULLM, bv, off);
            int   oi = __shfl_xor_sync(FULLM, bi, off);
            if (ov > bv || (ov == bv && oi < bi)) { bv = ov; bi = oi; }
        }
        if (lane == 0) { outv[k] = bv; outi[k] = bi; }
#pragma unroll
        for (int c = 0; c < 4; c++)
            if (mv[c] == bv && mi[c] == bi) { mv[c] = -FLT_MAX; mi[c] = INT_MAX; }
    }
}

// ---------------- Kernel 2: reduce candidates, do beam-search selection ------
__global__ void __launch_bounds__(256)
k2_select(const float* __restrict__ alive_lp, const float* __restrict__ fin_lp,
          const int* __restrict__ still_prompt,
          const int* __restrict__ is_first,
          const int* __restrict__ cur_pos_p, float* __restrict__ out) {
    int p = blockIdx.x;
    int t = threadIdx.x, w = t >> 5, lane = t & 31;

    __shared__ float sv[8][16];  __shared__ int si[8][16];
    __shared__ float sv0[8][16]; __shared__ int si0[8][16];
    __shared__ float fv[16];  __shared__ int fi[16];
    __shared__ float fv0[16]; __shared__ int fi0[16];

    if (lane < 16) {
        sv[w][lane] = -FLT_MAX;  si[w][lane] = INT_MAX;
        sv0[w][lane] = -FLT_MAX; si0[w][lane] = INT_MAX;
    }
    __syncwarp();

    {   // main candidates: 2048, warp w scans 256
        float th = -FLT_MAX; int thi = INT_MAX;
        for (int j = lane; j < 256; j += 32) {
            int a = p * NCAND + w * 256 + j;
            topk_insert(g_cand_val[a], g_cand_idx[a], th, thi, sv[w], si[w]);
        }
    }
    {   // beam0 candidates: 256, warp w scans 32 (one per lane)
        float th = -FLT_MAX; int thi = INT_MAX;
        int a = p * NC0 + w * 32 + lane;
        topk_insert(g_c0_val[a], g_c0_idx[a], th, thi, sv0[w], si0[w]);
    }
    __syncthreads();
    if (w == 0) warp_merge128(&sv[0][0],  &si[0][0],  fv,  fi);
    if (w == 1) warp_merge128(&sv0[0][0], &si0[0][0], fv0, fi0);
    __syncthreads();

    if (t == 0) {
        int cp = *cur_pos_p;
        bool sp = still_prompt[p] != 0;
        bool first = is_first[p] != 0;

        float lp16[16]; int tok16[16], beam16[16]; bool fin16[16];
        for (int k = 0; k < 16; k++) {
            int idx = fi[k];
            int bm = idx / V_;
            beam16[k] = bm;
            tok16[k]  = idx - bm * V_;
            lp16[k]   = logf(fv[k]);          // log(p*e^a) == a + log p
        }
        if (first) {
            float al0 = alive_lp[p * D_];
            for (int k = 0; k < 16; k++) {
                tok16[k] = fi0[k];            // flat idx within beam 0 == token
                lp16[k]  = al0 + logf(fv0[k]);
            }
        }
        for (int k = 0; k < 16; k++) fin16[k] = (tok16[k] == EOS_ID);

        // alive: top-8 of lp + finished*(-1e7)
        float am[16];
        for (int k = 0; k < 16; k++) am[k] = lp16[k] + (fin16[k] ? -MASK_INF : 0.0f);
        int na[8]; float nav[8]; bool used[16];
        for (int k = 0; k < 16; k++) used[k] = false;
        for (int j = 0; j < 8; j++) {
            int bi = -1; float bv = 0.0f;
            for (int k = 0; k < 16; k++)
                if (!used[k] && (bi < 0 || am[k] > bv)) { bi = k; bv = am[k]; }
            used[bi] = true; na[j] = bi; nav[j] = bv;
        }

        // finished: top-8 of [fin_lp(8), lp + !finished*(-1e7) (16)]
        float cl[24];
        for (int j = 0; j < 8; j++) cl[j] = fin_lp[p * D_ + j];
        for (int k = 0; k < 16; k++) cl[8 + k] = lp16[k] + (fin16[k] ? 0.0f : -MASK_INF);
        int nf[8]; float nfv[8]; bool used2[24];
        for (int k = 0; k < 24; k++) used2[k] = false;
        for (int j = 0; j < 8; j++) {
            int bi = -1; float bv = 0.0f;
            for (int k = 0; k < 24; k++)
                if (!used2[k] && (bi < 0 || cl[k] > bv)) { bi = k; bv = cl[k]; }
            used2[bi] = true; nf[j] = bi; nfv[j] = bv;
        }

        for (int j = 0; j < 8; j++) {
            out[OFF_ATTN + p * D_ + j] = sp ? (float)j : (float)beam16[na[j]];
            out[OFF_ALP  + p * D_ + j] = sp ? alive_lp[p * D_ + j] : nav[j];
            out[OFF_FLP  + p * D_ + j] = sp ? fin_lp[p * D_ + j]   : nfv[j];

            int4 da, df;
            if (sp) {
                da = make_int4(0, j, 0, -1);
                df = make_int4(1, j, 0, -1);
            } else {
                da = make_int4(0, beam16[na[j]], tok16[na[j]], cp);
                if (nf[j] < 8) df = make_int4(1, nf[j], 0, -1);
                else { int k = nf[j] - 8; df = make_int4(0, beam16[k], tok16[k], cp); }
            }
            g_desc[p * D_ + j] = da;
            g_desc[P_ * D_ + p * D_ + j] = df;
        }
    }
}

// ---------------- Kernel 3: gather output sequences --------------------------
__global__ void __launch_bounds__(256)
k3_gather(const int* __restrict__ alive_seq, const int* __restrict__ fin_seq,
          float* __restrict__ out) {
    int r = blockIdx.x;                       // 0..511
    int4 dsc = g_desc[r];
    bool isAlive = r < P_ * D_;
    int rr = isAlive ? r : r - P_ * D_;
    int p = rr >> 3;
    const int* srcbase = (dsc.x ? fin_seq : alive_seq) + (long)(p * D_ + dsc.y) * S_;
    long dst = (isAlive ? (long)OFF_ASEQ : (long)OFF_FSEQ) + (long)rr * S_;
    const int4* s4 = (const int4*)srcbase;
    float4* o4 = (float4*)(out + dst);
    int subpos = dsc.w, tok = dsc.z;
    for (int j = threadIdx.x; j < S_ / 4; j += 256) {
        int4 v = s4[j];
        int base = j * 4;
        if (subpos >= base && subpos < base + 4) {
            int* vp = (int*)&v;
            vp[subpos - base] = tok;
        }
        o4[j] = make_float4((float)v.x, (float)v.y, (float)v.z, (float)v.w);
    }
}

extern "C" void kernel_launch(void* const* d_in, const int* in_sizes, int n_in,
                              void* d_out, int out_size) {
    const float* probs        = (const float*)d_in[0];
    const int*   alive_seq    = (const int*)d_in[1];
    const int*   fin_seq      = (const int*)d_in[2];
    const float* alive_lp     = (const float*)d_in[3];
    const float* fin_lp       = (const float*)d_in[4];
    const int*   still_prompt = (const int*)d_in[5];
    const int*   is_first     = (const int*)d_in[6];
    const int*   cur_pos      = (const int*)d_in[7];
    float* out = (float*)d_out;

    k0_tau<<<P_, 512>>>(probs, alive_lp);
    k1_scan<<<P_ * NBLK, 256>>>(probs, alive_lp);
    k2_select<<<P_, 256>>>(alive_lp, fin_lp, still_prompt, is_first, cur_pos, out);
    k3_gather<<<2 * P_ * D_, 256>>>(alive_seq, fin_seq, out);
}

// round 7
// speedup vs baseline: 9.7830x; 9.7830x over previous
#include <cuda_runtime.h>
#include <cfloat>
#include <climits>
#include <math.h>

// Beam search step: P=32 prompts, D=8 beams, V=128000, S=2048.
// Ordering by alive_lp + log(p) == ordering by m = p * exp(alive_lp) (monotone).
// k0: tau = 16th-largest of 128 scaled chunk maxima (valid & tight bound on the
//     global 16th scaled value); tau0 likewise for beam-0 raw (full coverage).
// k1: stateless filter — elements >= tau are appended to a global candidate
//     buffer (atomicAdd). Fast path: 4 loads + 15 fmax + 1 fmul + 1 ballot /512.
// k2: exact top-16 over the few surviving candidates, then the selection.
// NOTE: all topk_insert call sites must have warp-uniform trip counts (it uses
// full-mask ballots); runtime-count loops use sentinel padding.

#define P_ 32
#define D_ 8
#define V_ 128000
#define S_ 2048
#define NBLK 16          // blocks per prompt in k1 (2 per beam)
#define CHUNK 64000      // elements per k1 block (V/2)
#define EOS_ID 2
#define MASK_INF 10000000.0f
#define PADV (-FLT_MAX)
#define CAP  32768       // candidate capacity per prompt (scaled list)
#define CAP0 8192        // candidate capacity per prompt (beam-0 raw list)

// output layout (flat float32, tuple concat order)
#define OFF_ATTN 0
#define OFF_ASEQ 256
#define OFF_ALP  524544
#define OFF_FSEQ 524800
#define OFF_FLP  1049088

__device__ float g_tau[P_];
__device__ float g_tau0[P_];
__device__ int   g_cnt[P_];
__device__ int   g_cnt0[P_];
__device__ float g_cv[P_ * CAP];
__device__ int   g_ci[P_ * CAP];
__device__ float g_c0v[P_ * CAP0];
__device__ int   g_c0i[P_ * CAP0];
__device__ int4  g_desc[2 * P_ * D_];   // {buf(0=alive,1=fin), src_beam, token, subpos(-1 none)}

#define FULLM 0xffffffffu

__device__ __forceinline__ float max4(float4 v) {
    return fmaxf(fmaxf(v.x, v.y), fmaxf(v.z, v.w));
}

// Warp-cooperative insertion into a shared sorted top-16 list (desc value, asc index).
// MUST be called by all 32 lanes the same number of times (full-mask ballot).
__device__ __forceinline__ void topk_insert(float v, int idx, float& th, int& thi,
                                            volatile float* lv, volatile int* li) {
    int lane = threadIdx.x & 31;
    bool want = (v > th) || (v == th && idx < thi);
    while (true) {
        unsigned mask = __ballot_sync(FULLM, want);
        if (!mask) break;
        int leader = __ffs(mask) - 1;
        if (lane == leader) {
            int pos = 16;
            for (int j = 15; j >= 0; j--) {
                if ((v > lv[j]) || (v == lv[j] && idx < li[j])) pos = j; else break;
            }
            if (pos < 16) {
                for (int j = 15; j > pos; j--) { lv[j] = lv[j-1]; li[j] = li[j-1]; }
                lv[pos] = v; li[pos] = idx;
            }
            want = false;
        }
        __syncwarp();
        th = lv[15]; thi = li[15];
        want = want && ((v > th) || (v == th && idx < thi));
    }
}

// Merge 128 shared values into sorted top-16 (one warp).
__device__ __forceinline__ void warp_merge128(volatile float* svals, volatile int* sidx,
                                              volatile float* outv, volatile int* outi) {
    int lane = threadIdx.x & 31;
    float mv[4]; int mi[4];
#pragma unroll
    for (int c = 0; c < 4; c++) { mv[c] = svals[lane * 4 + c]; mi[c] = sidx[lane * 4 + c]; }
    for (int k = 0; k < 16; k++) {
        float bv = mv[0]; int bi = mi[0];
#pragma unroll
        for (int c = 1; c < 4; c++)
            if (mv[c] > bv || (mv[c] == bv && mi[c] < bi)) { bv = mv[c]; bi = mi[c]; }
#pragma unroll
        for (int off = 16; off; off >>= 1) {
            float ov = __shfl_xor_sync(FULLM, bv, off);
            int   oi = __shfl_xor_sync(FULLM, bi, off);
            if (ov > bv || (ov == bv && oi < bi)) { bv = ov; bi = oi; }
        }
        if (lane == 0) { outv[k] = bv; outi[k] = bi; }
#pragma unroll
        for (int c = 0; c < 4; c++)
            if (mv[c] == bv && mi[c] == bi) { mv[c] = -FLT_MAX; mi[c] = INT_MAX; }
    }
}

// ---------------- Kernel 0: tight thresholds + counter reset -----------------
// tau  = 16th largest of 128 scaled chunk maxima (16 chunks/beam, 1000 elems at
//        stride 8000 -> 1/8 sample of each beam; bound valid for any disjoint chunks).
// tau0 = 16th largest of 128 raw chunk maxima of beam 0 (1000 elems each, full cover).
__global__ void __launch_bounds__(512)
k0_tau(const float* __restrict__ probs, const float* __restrict__ alive_lp) {
    int p = blockIdx.x;
    int t = threadIdx.x, w = t >> 5, lane = t & 31;
    __shared__ float sA[128];
    __shared__ float sB[128];
    __shared__ int   sIdx[128];
    __shared__ float outv[16];  __shared__ int outi[16];
    __shared__ float outv0[16]; __shared__ int outi0[16];
    __shared__ float ssc[8];

    if (t < 8)   ssc[t] = expf(alive_lp[p * D_ + t]);
    if (t < 128) sIdx[t] = t;
    __syncthreads();

    for (int cc = w; cc < 128; cc += 16) {      // scaled chunks
        int d = cc >> 4, c = cc & 15;
        const float4* base = (const float4*)(probs + (long)(p * D_ + d) * V_ + c * 8000);
        float m = -FLT_MAX;
        for (int i = lane; i < 250; i += 32) m = fmaxf(m, max4(base[i]));
#pragma unroll
        for (int off = 16; off; off >>= 1) m = fmaxf(m, __shfl_xor_sync(FULLM, m, off));
        if (lane == 0) sA[cc] = m * ssc[d];
    }
    for (int cc = w; cc < 128; cc += 16) {      // beam-0 raw chunks (full coverage)
        const float4* base = (const float4*)(probs + (long)(p * D_) * V_ + cc * 1000);
        float m = -FLT_MAX;
        for (int i = lane; i < 250; i += 32) m = fmaxf(m, max4(base[i]));
#pragma unroll
        for (int off = 16; off; off >>= 1) m = fmaxf(m, __shfl_xor_sync(FULLM, m, off));
        if (lane == 0) sB[cc] = m;
    }
    __syncthreads();
    if (w == 0) warp_merge128(sA, sIdx, outv, outi);
    if (w == 1) warp_merge128(sB, sIdx, outv0, outi0);
    __syncthreads();
    if (t == 0) {
        g_tau[p] = outv[15];
        g_tau0[p] = outv0[15];
        g_cnt[p] = 0; g_cnt0[p] = 0;
    }
}

// ---------------- Kernel 1: scan probs, append >=tau candidates --------------
__global__ void __launch_bounds__(256)
k1_scan(const float* __restrict__ probs, const float* __restrict__ alive_lp) {
    int blk = blockIdx.x;
    int p = blk >> 4;
    int b = blk & 15;
    int d = b >> 1;
    int half = b & 1;
    int t = threadIdx.x;

    float scale = expf(alive_lp[p * D_ + d]);
    float tau  = g_tau[p];
    float tau0 = g_tau0[p];
    const float4* b4 = (const float4*)(probs + (long)(p * D_ + d) * V_ + half * CHUNK);
    int fb0 = d * V_ + half * CHUNK;
    const int N4 = CHUNK / 4;                 // 16000 float4s per block
    bool do0 = (d == 0);
    const float4 pad4 = make_float4(PADV, PADV, PADV, PADV);

    for (int j0 = t; j0 < N4; j0 += 1024) {
        int j1 = j0 + 256, j2 = j0 + 512, j3 = j0 + 768;
        float4 va = __ldcs(b4 + j0);
        float4 vb = (j1 < N4) ? __ldcs(b4 + j1) : pad4;
        float4 vc = (j2 < N4) ? __ldcs(b4 + j2) : pad4;
        float4 vd = (j3 < N4) ? __ldcs(b4 + j3) : pad4;

        float vmax = fmaxf(fmaxf(max4(va), max4(vb)), fmaxf(max4(vc), max4(vd)));
        bool trig = (vmax * scale >= tau) || (do0 && vmax >= tau0);

        if (__ballot_sync(FULLM, trig)) {     // rare with tight tau
            float4 q[4] = {va, vb, vc, vd};
            int js[4] = {j0, j1, j2, j3};
#pragma unroll
            for (int u = 0; u < 4; u++) {
                if (js[u] >= N4) continue;
                int fb = fb0 + js[u] * 4;
                float vx[4] = {q[u].x, q[u].y, q[u].z, q[u].w};
#pragma unroll
                for (int c = 0; c < 4; c++) {
                    float sval = vx[c] * scale;
                    if (sval >= tau) {
                        int pos = atomicAdd(&g_cnt[p], 1);
                        if (pos < CAP) { g_cv[p * CAP + pos] = sval; g_ci[p * CAP + pos] = fb + c; }
                    }
                    if (do0 && vx[c] >= tau0) {   // d==0: flat idx == token id
                        int pos = atomicAdd(&g_cnt0[p], 1);
                        if (pos < CAP0) { g_c0v[p * CAP0 + pos] = vx[c]; g_c0i[p * CAP0 + pos] = fb + c; }
                    }
                }
            }
        }
    }
}

// ---------------- Kernel 2: exact top-16 over candidates + selection ---------
__global__ void __launch_bounds__(256)
k2_select(const float* __restrict__ alive_lp, const float* __restrict__ fin_lp,
          const int* __restrict__ still_prompt,
          const int* __restrict__ is_first,
          const int* __restrict__ cur_pos_p, float* __restrict__ out) {
    int p = blockIdx.x;
    int t = threadIdx.x, w = t >> 5, lane = t & 31;

    __shared__ float sv[8][16];  __shared__ int si[8][16];
    __shared__ float sv0[8][16]; __shared__ int si0[8][16];
    __shared__ float fv[16];  __shared__ int fi[16];
    __shared__ float fv0[16]; __shared__ int fi0[16];

    if (lane < 16) {
        sv[w][lane] = -FLT_MAX;  si[w][lane] = INT_MAX;
        sv0[w][lane] = -FLT_MAX; si0[w][lane] = INT_MAX;
    }
    __syncwarp();

    int cnt  = min(g_cnt[p], CAP);
    int cnt0 = min(g_cnt0[p], CAP0);

    {   // main candidates: warp-uniform trip count, sentinel-padded lanes
        float th = -FLT_MAX; int thi = INT_MAX;
        for (int jb = w * 32; jb < cnt; jb += 256) {
            int j = jb + lane;
            bool ok = (j < cnt);
            float v = ok ? g_cv[p * CAP + j] : -FLT_MAX;
            int   i = ok ? g_ci[p * CAP + j] : INT_MAX;
            topk_insert(v, i, th, thi, sv[w], si[w]);
        }
    }
    {   // beam-0 candidates
        float th = -FLT_MAX; int thi = INT_MAX;
        for (int jb = w * 32; jb < cnt0; jb += 256) {
            int j = jb + lane;
            bool ok = (j < cnt0);
            float v = ok ? g_c0v[p * CAP0 + j] : -FLT_MAX;
            int   i = ok ? g_c0i[p * CAP0 + j] : INT_MAX;
            topk_insert(v, i, th, thi, sv0[w], si0[w]);
        }
    }
    __syncthreads();
    if (w == 0) warp_merge128(&sv[0][0],  &si[0][0],  fv,  fi);
    if (w == 1) warp_merge128(&sv0[0][0], &si0[0][0], fv0, fi0);
    __syncthreads();

    if (t == 0) {
        int cp = *cur_pos_p;
        bool sp = still_prompt[p] != 0;
        bool first = is_first[p] != 0;

        float lp16[16]; int tok16[16], beam16[16]; bool fin16[16];
        for (int k = 0; k < 16; k++) {
            int idx = fi[k];
            int bm = idx / V_;
            beam16[k] = bm;
            tok16[k]  = idx - bm * V_;
            lp16[k]   = logf(fv[k]);          // log(p*e^a) == a + log p
        }
        if (first) {
            float al0 = alive_lp[p * D_];
            for (int k = 0; k < 16; k++) {
                tok16[k] = fi0[k];            // flat idx within beam 0 == token
                lp16[k]  = al0 + logf(fv0[k]);
            }
        }
        for (int k = 0; k < 16; k++) fin16[k] = (tok16[k] == EOS_ID);

        // alive: top-8 of lp + finished*(-1e7)
        float am[16];
        for (int k = 0; k < 16; k++) am[k] = lp16[k] + (fin16[k] ? -MASK_INF : 0.0f);
        int na[8]; float nav[8]; bool used[16];
        for (int k = 0; k < 16; k++) used[k] = false;
        for (int j = 0; j < 8; j++) {
            int bi = -1; float bv = 0.0f;
            for (int k = 0; k < 16; k++)
                if (!used[k] && (bi < 0 || am[k] > bv)) { bi = k; bv = am[k]; }
            used[bi] = true; na[j] = bi; nav[j] = bv;
        }

        // finished: top-8 of [fin_lp(8), lp + !finished*(-1e7) (16)]
        float cl[24];
        for (int j = 0; j < 8; j++) cl[j] = fin_lp[p * D_ + j];
        for (int k = 0; k < 16; k++) cl[8 + k] = lp16[k] + (fin16[k] ? 0.0f : -MASK_INF);
        int nf[8]; float nfv[8]; bool used2[24];
        for (int k = 0; k < 24; k++) used2[k] = false;
        for (int j = 0; j < 8; j++) {
            int bi = -1; float bv = 0.0f;
            for (int k = 0; k < 24; k++)
                if (!used2[k] && (bi < 0 || cl[k] > bv)) { bi = k; bv = cl[k]; }
            used2[bi] = true; nf[j] = bi; nfv[j] = bv;
        }

        for (int j = 0; j < 8; j++) {
            out[OFF_ATTN + p * D_ + j] = sp ? (float)j : (float)beam16[na[j]];
            out[OFF_ALP  + p * D_ + j] = sp ? alive_lp[p * D_ + j] : nav[j];
            out[OFF_FLP  + p * D_ + j] = sp ? fin_lp[p * D_ + j]   : nfv[j];

            int4 da, df;
            if (sp) {
                da = make_int4(0, j, 0, -1);
                df = make_int4(1, j, 0, -1);
            } else {
                da = make_int4(0, beam16[na[j]], tok16[na[j]], cp);
                if (nf[j] < 8) df = make_int4(1, nf[j], 0, -1);
                else { int k = nf[j] - 8; df = make_int4(0, beam16[k], tok16[k], cp); }
            }
            g_desc[p * D_ + j] = da;
            g_desc[P_ * D_ + p * D_ + j] = df;
        }
    }
}

// ---------------- Kernel 3: gather output sequences --------------------------
__global__ void __launch_bounds__(256)
k3_gather(const int* __restrict__ alive_seq, const int* __restrict__ fin_seq,
          float* __restrict__ out) {
    int r = blockIdx.x;                       // 0..511
    int4 dsc = g_desc[r];
    bool isAlive = r < P_ * D_;
    int rr = isAlive ? r : r - P_ * D_;
    int p = rr >> 3;
    const int* srcbase = (dsc.x ? fin_seq : alive_seq) + (long)(p * D_ + dsc.y) * S_;
    long dst = (isAlive ? (long)OFF_ASEQ : (long)OFF_FSEQ) + (long)rr * S_;
    const int4* s4 = (const int4*)srcbase;
    float4* o4 = (float4*)(out + dst);
    int subpos = dsc.w, tok = dsc.z;
    for (int j = threadIdx.x; j < S_ / 4; j += 256) {
        int4 v = s4[j];
        int base = j * 4;
        if (subpos >= base && subpos < base + 4) {
            int* vp = (int*)&v;
            vp[subpos - base] = tok;
        }
        o4[j] = make_float4((float)v.x, (float)v.y, (float)v.z, (float)v.w);
    }
}

extern "C" void kernel_launch(void* const* d_in, const int* in_sizes, int n_in,
                              void* d_out, int out_size) {
    const float* probs        = (const float*)d_in[0];
    const int*   alive_seq    = (const int*)d_in[1];
    const int*   fin_seq      = (const int*)d_in[2];
    const float* alive_lp     = (const float*)d_in[3];
    const float* fin_lp       = (const float*)d_in[4];
    const int*   still_prompt = (const int*)d_in[5];
    const int*   is_first     = (const int*)d_in[6];
    const int*   cur_pos      = (const int*)d_in[7];
    float* out = (float*)d_out;

    k0_tau<<<P_, 512>>>(probs, alive_lp);
    k1_scan<<<P_ * NBLK, 256>>>(probs, alive_lp);
    k2_select<<<P_, 256>>>(alive_lp, fin_lp, still_prompt, is_first, cur_pos, out);
    k3_gather<<<2 * P_ * D_, 256>>>(alive_seq, fin_seq, out);
}

// round 8
// speedup vs baseline: 11.5003x; 1.1755x over previous
#include <cuda_runtime.h>
#include <cfloat>
#include <climits>
#include <math.h>

// Beam search step: P=32 prompts, D=8 beams, V=128000, S=2048.
// Ordering by alive_lp + log(p) == ordering by m = p * exp(alive_lp) (monotone).
// k1 (fused): pass 1 computes 32 sub-chunk maxima over the block's 256KB chunk
//   (DRAM); tau_b = 16th largest of them (<= local 16th <= global 16th, so no
//   top-16 element is ever dropped). pass 2 re-reads (L2-resident) and appends
//   elements >= tau_b to per-prompt candidate buffers. still_prompt blocks exit
//   immediately (outputs are passthrough). Beam-0 raw list shares the SAME
//   compare (scale>0 monotone), emitted only when is_first.
// k2: exact top-16 (value desc, idx asc) over candidates + selection; resets
//   counters for the next graph replay.
// k3: gathers/converts the 512 output sequence rows.

#define P_ 32
#define D_ 8
#define V_ 128000
#define S_ 2048
#define NBLK 16          // blocks per prompt in k1 (2 per beam)
#define CHUNK 64000      // elements per k1 block (V/2)
#define NSUB 32          // sub-chunks per block (2000 elems each)
#define EOS_ID 2
#define MASK_INF 10000000.0f
#define PADV (-FLT_MAX)
#define CAP  32768       // candidate capacity per prompt (scaled list)
#define CAP0 8192        // candidate capacity per prompt (beam-0 raw list)

// output layout (flat float32, tuple concat order)
#define OFF_ATTN 0
#define OFF_ASEQ 256
#define OFF_ALP  524544
#define OFF_FSEQ 524800
#define OFF_FLP  1049088

__device__ int   g_cnt[P_];              // zero-initialized at load; k2 resets
__device__ int   g_cnt0[P_];
__device__ float g_cv[P_ * CAP];
__device__ int   g_ci[P_ * CAP];
__device__ float g_c0v[P_ * CAP0];
__device__ int   g_c0i[P_ * CAP0];
__device__ int4  g_desc[2 * P_ * D_];    // {buf(0=alive,1=fin), src_beam, token, subpos(-1 none)}

#define FULLM 0xffffffffu

__device__ __forceinline__ float max4(float4 v) {
    return fmaxf(fmaxf(v.x, v.y), fmaxf(v.z, v.w));
}

// Warp-cooperative insertion into a shared sorted top-16 list (desc value, asc index).
// MUST be called by all 32 lanes the same number of times (full-mask ballot).
__device__ __forceinline__ void topk_insert(float v, int idx, float& th, int& thi,
                                            volatile float* lv, volatile int* li) {
    int lane = threadIdx.x & 31;
    bool want = (v > th) || (v == th && idx < thi);
    while (true) {
        unsigned mask = __ballot_sync(FULLM, want);
        if (!mask) break;
        int leader = __ffs(mask) - 1;
        if (lane == leader) {
            int pos = 16;
            for (int j = 15; j >= 0; j--) {
                if ((v > lv[j]) || (v == lv[j] && idx < li[j])) pos = j; else break;
            }
            if (pos < 16) {
                for (int j = 15; j > pos; j--) { lv[j] = lv[j-1]; li[j] = li[j-1]; }
                lv[pos] = v; li[pos] = idx;
            }
            want = false;
        }
        __syncwarp();
        th = lv[15]; thi = li[15];
        want = want && ((v > th) || (v == th && idx < thi));
    }
}

// Merge 128 shared values into sorted top-16 (one warp).
__device__ __forceinline__ void warp_merge128(volatile float* svals, volatile int* sidx,
                                              volatile float* outv, volatile int* outi) {
    int lane = threadIdx.x & 31;
    float mv[4]; int mi[4];
#pragma unroll
    for (int c = 0; c < 4; c++) { mv[c] = svals[lane * 4 + c]; mi[c] = sidx[lane * 4 + c]; }
    for (int k = 0; k < 16; k++) {
        float bv = mv[0]; int bi = mi[0];
#pragma unroll
        for (int c = 1; c < 4; c++)
            if (mv[c] > bv || (mv[c] == bv && mi[c] < bi)) { bv = mv[c]; bi = mi[c]; }
#pragma unroll
        for (int off = 16; off; off >>= 1) {
            float ov = __shfl_xor_sync(FULLM, bv, off);
            int   oi = __shfl_xor_sync(FULLM, bi, off);
            if (ov > bv || (ov == bv && oi < bi)) { bv = ov; bi = oi; }
        }
        if (lane == 0) { outv[k] = bv; outi[k] = bi; }
#pragma unroll
        for (int c = 0; c < 4; c++)
            if (mv[c] == bv && mi[c] == bi) { mv[c] = -FLT_MAX; mi[c] = INT_MAX; }
    }
}

// ---------------- Kernel 1: self-thresholding scan + candidate append --------
__global__ void __launch_bounds__(256)
k1_scan(const float* __restrict__ probs, const float* __restrict__ alive_lp,
        const int* __restrict__ still_prompt, const int* __restrict__ is_first) {
    int blk = blockIdx.x;
    int p = blk >> 4;
    if (still_prompt[p]) return;              // passthrough prompt: no work
    int b = blk & 15;
    int d = b >> 1;
    int half = b & 1;
    int t = threadIdx.x, w = t >> 5, lane = t & 31;

    __shared__ float scm[NSUB];
    __shared__ float s_tau;

    const float4* base = (const float4*)(probs + (long)(p * D_ + d) * V_ + half * CHUNK);
    const int N4 = CHUNK / 4;                 // 16000 float4s
    const int SUB4 = N4 / NSUB;               // 500 float4s per sub-chunk

    // ---- pass 1: 32 sub-chunk maxima (DRAM read; stays resident in L2) ----
#pragma unroll
    for (int ss = 0; ss < NSUB / 8; ss++) {   // warp w -> sub-chunks w, w+8, w+16, w+24
        int s = w + ss * 8;
        const float4* sb = base + s * SUB4;
        float m = -FLT_MAX;
        for (int i = lane; i < SUB4; i += 32) m = fmaxf(m, max4(sb[i]));
#pragma unroll
        for (int off = 16; off; off >>= 1) m = fmaxf(m, __shfl_xor_sync(FULLM, m, off));
        if (lane == 0) scm[s] = m;
    }
    __syncthreads();

    // ---- tau_b = 16th largest of the 32 maxima (warp 0, argmax-invalidate) ----
    if (w == 0) {
        float v = scm[lane];
        float last = -FLT_MAX;
#pragma unroll
        for (int k = 0; k < 16; k++) {
            float bv = v; int bl = lane;
#pragma unroll
            for (int off = 16; off; off >>= 1) {
                float ov = __shfl_xor_sync(FULLM, bv, off);
                int   ol = __shfl_xor_sync(FULLM, bl, off);
                if (ov > bv || (ov == bv && ol < bl)) { bv = ov; bl = ol; }
            }
            last = bv;
            if (lane == bl) v = -FLT_MAX;
        }
        if (lane == 0) s_tau = last;
    }
    __syncthreads();

    float tauR = s_tau;                       // raw-space threshold (shared by both lists)
    float scale = expf(alive_lp[p * D_ + d]);
    bool do0 = (d == 0) && (is_first[p] != 0);
    int fb0 = d * V_ + half * CHUNK;
    const float4 pad4 = make_float4(PADV, PADV, PADV, PADV);

    // ---- pass 2: filter >= tauR (L2-resident re-read), append candidates ----
    for (int j0 = t; j0 < N4; j0 += 1024) {
        int j1 = j0 + 256, j2 = j0 + 512, j3 = j0 + 768;
        float4 va = base[j0];
        float4 vb = (j1 < N4) ? base[j1] : pad4;
        float4 vc = (j2 < N4) ? base[j2] : pad4;
        float4 vd = (j3 < N4) ? base[j3] : pad4;

        float vmax = fmaxf(fmaxf(max4(va), max4(vb)), fmaxf(max4(vc), max4(vd)));

        if (__ballot_sync(FULLM, vmax >= tauR)) {     // rare
            float4 q[4] = {va, vb, vc, vd};
            int js[4] = {j0, j1, j2, j3};
#pragma unroll
            for (int u = 0; u < 4; u++) {
                if (js[u] >= N4) continue;
                int fb = fb0 + js[u] * 4;
                float vx[4] = {q[u].x, q[u].y, q[u].z, q[u].w};
#pragma unroll
                for (int c = 0; c < 4; c++) {
                    if (vx[c] >= tauR) {
                        int pos = atomicAdd(&g_cnt[p], 1);
                        if (pos < CAP) { g_cv[p * CAP + pos] = vx[c] * scale; g_ci[p * CAP + pos] = fb + c; }
                        if (do0) {                    // d==0: flat idx == token id
                            int pos0 = atomicAdd(&g_cnt0[p], 1);
                            if (pos0 < CAP0) { g_c0v[p * CAP0 + pos0] = vx[c]; g_c0i[p * CAP0 + pos0] = fb + c; }
                        }
                    }
                }
            }
        }
    }
}

// ---------------- Kernel 2: exact top-16 over candidates + selection ---------
__global__ void __launch_bounds__(256)
k2_select(const float* __restrict__ alive_lp, const float* __restrict__ fin_lp,
          const int* __restrict__ still_prompt,
          const int* __restrict__ is_first,
          const int* __restrict__ cur_pos_p, float* __restrict__ out) {
    int p = blockIdx.x;
    int t = threadIdx.x, w = t >> 5, lane = t & 31;

    __shared__ float sv[8][16];  __shared__ int si[8][16];
    __shared__ float sv0[8][16]; __shared__ int si0[8][16];
    __shared__ float fv[16];  __shared__ int fi[16];
    __shared__ float fv0[16]; __shared__ int fi0[16];

    if (lane < 16) {
        sv[w][lane] = -FLT_MAX;  si[w][lane] = INT_MAX;
        sv0[w][lane] = -FLT_MAX; si0[w][lane] = INT_MAX;
    }
    __syncwarp();

    int cnt  = min(g_cnt[p], CAP);
    int cnt0 = min(g_cnt0[p], CAP0);

    {   // main candidates: warp-uniform trip count, sentinel-padded lanes
        float th = -FLT_MAX; int thi = INT_MAX;
        for (int jb = w * 32; jb < cnt; jb += 256) {
            int j = jb + lane;
            bool ok = (j < cnt);
            float v = ok ? g_cv[p * CAP + j] : -FLT_MAX;
            int   i = ok ? g_ci[p * CAP + j] : INT_MAX;
            topk_insert(v, i, th, thi, sv[w], si[w]);
        }
    }
    {   // beam-0 candidates
        float th = -FLT_MAX; int thi = INT_MAX;
        for (int jb = w * 32; jb < cnt0; jb += 256) {
            int j = jb + lane;
            bool ok = (j < cnt0);
            float v = ok ? g_c0v[p * CAP0 + j] : -FLT_MAX;
            int   i = ok ? g_c0i[p * CAP0 + j] : INT_MAX;
            topk_insert(v, i, th, thi, sv0[w], si0[w]);
        }
    }
    __syncthreads();
    if (w == 0) warp_merge128(&sv[0][0],  &si[0][0],  fv,  fi);
    if (w == 1) warp_merge128(&sv0[0][0], &si0[0][0], fv0, fi0);
    __syncthreads();

    if (t == 0) {
        g_cnt[p] = 0; g_cnt0[p] = 0;          // reset for next graph replay
        int cp = *cur_pos_p;
        bool sp = still_prompt[p] != 0;
        bool first = is_first[p] != 0;

        float lp16[16]; int tok16[16], beam16[16]; bool fin16[16];
        for (int k = 0; k < 16; k++) {
            int idx = fi[k];
            int bm = idx / V_;
            beam16[k] = bm;
            tok16[k]  = idx - bm * V_;
            lp16[k]   = logf(fv[k]);          // log(p*e^a) == a + log p
        }
        if (first) {
            float al0 = alive_lp[p * D_];
            for (int k = 0; k < 16; k++) {
                tok16[k] = fi0[k];            // flat idx within beam 0 == token
                lp16[k]  = al0 + logf(fv0[k]);
            }
        }
        for (int k = 0; k < 16; k++) fin16[k] = (tok16[k] == EOS_ID);

        // alive: top-8 of lp + finished*(-1e7)
        float am[16];
        for (int k = 0; k < 16; k++) am[k] = lp16[k] + (fin16[k] ? -MASK_INF : 0.0f);
        int na[8]; float nav[8]; bool used[16];
        for (int k = 0; k < 16; k++) used[k] = false;
        for (int j = 0; j < 8; j++) {
            int bi = -1; float bv = 0.0f;
            for (int k = 0; k < 16; k++)
                if (!used[k] && (bi < 0 || am[k] > bv)) { bi = k; bv = am[k]; }
            used[bi] = true; na[j] = bi; nav[j] = bv;
        }

        // finished: top-8 of [fin_lp(8), lp + !finished*(-1e7) (16)]
        float cl[24];
        for (int j = 0; j < 8; j++) cl[j] = fin_lp[p * D_ + j];
        for (int k = 0; k < 16; k++) cl[8 + k] = lp16[k] + (fin16[k] ? 0.0f : -MASK_INF);
        int nf[8]; float nfv[8]; bool used2[24];
        for (int k = 0; k < 24; k++) used2[k] = false;
        for (int j = 0; j < 8; j++) {
            int bi = -1; float bv = 0.0f;
            for (int k = 0; k < 24; k++)
                if (!used2[k] && (bi < 0 || cl[k] > bv)) { bi = k; bv = cl[k]; }
            used2[bi] = true; nf[j] = bi; nfv[j] = bv;
        }

        for (int j = 0; j < 8; j++) {
            out[OFF_ATTN + p * D_ + j] = sp ? (float)j : (float)beam16[na[j]];
            out[OFF_ALP  + p * D_ + j] = sp ? alive_lp[p * D_ + j] : nav[j];
            out[OFF_FLP  + p * D_ + j] = sp ? fin_lp[p * D_ + j]   : nfv[j];

            int4 da, df;
            if (sp) {
                da = make_int4(0, j, 0, -1);
                df = make_int4(1, j, 0, -1);
            } else {
                da = make_int4(0, beam16[na[j]], tok16[na[j]], cp);
                if (nf[j] < 8) df = make_int4(1, nf[j], 0, -1);
                else { int k = nf[j] - 8; df = make_int4(0, beam16[k], tok16[k], cp); }
            }
            g_desc[p * D_ + j] = da;
            g_desc[P_ * D_ + p * D_ + j] = df;
        }
    }
}

// ---------------- Kernel 3: gather output sequences --------------------------
__global__ void __launch_bounds__(256)
k3_gather(const int* __restrict__ alive_seq, const int* __restrict__ fin_seq,
          float* __restrict__ out) {
    int r = blockIdx.x;                       // 0..511
    int4 dsc = g_desc[r];
    bool isAlive = r < P_ * D_;
    int rr = isAlive ? r : r - P_ * D_;
    int p = rr >> 3;
    const int* srcbase = (dsc.x ? fin_seq : alive_seq) + (long)(p * D_ + dsc.y) * S_;
    long dst = (isAlive ? (long)OFF_ASEQ : (long)OFF_FSEQ) + (long)rr * S_;
    const int4* s4 = (const int4*)srcbase;
    float4* o4 = (float4*)(out + dst);
    int subpos = dsc.w, tok = dsc.z;
    for (int j = threadIdx.x; j < S_ / 4; j += 256) {
        int4 v = s4[j];
        int base = j * 4;
        if (subpos >= base && subpos < base + 4) {
            int* vp = (int*)&v;
            vp[subpos - base] = tok;
        }
        o4[j] = make_float4((float)v.x, (float)v.y, (float)v.z, (float)v.w);
    }
}

extern "C" void kernel_launch(void* const* d_in, const int* in_sizes, int n_in,
                              void* d_out, int out_size) {
    const float* probs        = (const float*)d_in[0];
    const int*   alive_seq    = (const int*)d_in[1];
    const int*   fin_seq      = (const int*)d_in[2];
    const float* alive_lp     = (const float*)d_in[3];
    const float* fin_lp       = (const float*)d_in[4];
    const int*   still_prompt = (const int*)d_in[5];
    const int*   is_first     = (const int*)d_in[6];
    const int*   cur_pos      = (const int*)d_in[7];
    float* out = (float*)d_out;

    k1_scan<<<P_ * NBLK, 256>>>(probs, alive_lp, still_prompt, is_first);
    k2_select<<<P_, 256>>>(alive_lp, fin_lp, still_prompt, is_first, cur_pos, out);
    k3_gather<<<2 * P_ * D_, 256>>>(alive_seq, fin_seq, out);
}